// round 11
// baseline (speedup 1.0000x reference)
#include <cuda_runtime.h>
#include <cstdint>

// FixedGaussianBlur: depthwise 21x21 Gaussian (sigma=3), reflect padding,
// x[32,3,512,512] f32 -> y[32,3,512,512] f32.
// R8 structure (64.2us best) + issue-diet:
//  - loader: constant-stride pointer walk (alu-pipe IADD, no div/wrap),
//    fast path for fully interior blocks
//  - horizontal: scalar FFMA-imm in place, P2 hoisted before the barrier
//    (3 syncthreads total instead of 4)
//  - vertical: packed fma.rn.f32x2, byte-pointer increments (no IMAD)

#define IMG_W 512
#define IMG_H 512
#define PAD 10
#define KS 21
#define TW 64
#define TH 128
#define SROWS 148
#define SCOLS 84
#define NTHREADS 512
#define NIMG 96
#define SMEM_BYTES (SROWS * SCOLS * 4)  // 49728

#define W0  0.13303900f
#define W1  0.12584950f
#define W2  0.10652928f
#define W3  0.08069223f
#define W4  0.05469397f
#define W5  0.03317359f
#define W6  0.01800488f
#define W7  0.00874446f
#define W8  0.00380033f
#define W9  0.00147793f
#define W10 0.00051432f

__device__ __forceinline__ float tap(int j) {
    constexpr float w[KS] = {W10, W9, W8, W7, W6, W5, W4, W3, W2, W1, W0,
                             W1, W2, W3, W4, W5, W6, W7, W8, W9, W10};
    return w[j];
}

__device__ __forceinline__ int reflect_idx(int i, int n) {
    i = (i < 0) ? -i : i;
    i = (i >= n) ? (2 * n - 2 - i) : i;
    return i;
}

__device__ __forceinline__ uint64_t bcast2(float f) {
    uint32_t b = __float_as_uint(f);
    return ((uint64_t)b << 32) | (uint64_t)b;
}

__device__ __forceinline__ void ffma2(uint64_t& d, uint64_t a, uint64_t b, uint64_t c) {
    asm("fma.rn.f32x2 %0, %1, %2, %3;" : "=l"(d) : "l"(a), "l"(b), "l"(c));
}

// 16-output horizontal filter: reads srow[0..35] via 9 LDS.128, scalar FFMA-imm.
__device__ __forceinline__ void hfilter16(const float* srow, float o[16]) {
    float v[36];
    const float4* p = reinterpret_cast<const float4*>(srow);
    #pragma unroll
    for (int q = 0; q < 9; ++q) {
        float4 t = p[q];
        v[4 * q + 0] = t.x; v[4 * q + 1] = t.y;
        v[4 * q + 2] = t.z; v[4 * q + 3] = t.w;
    }
    #pragma unroll
    for (int c = 0; c < 16; ++c) {
        float acc = v[c] * tap(0);
        #pragma unroll
        for (int j = 1; j < KS; ++j) acc = fmaf(v[c + j], tap(j), acc);
        o[c] = acc;
    }
}

__global__ __launch_bounds__(NTHREADS, 3)
void gauss_blur_fused(const float* __restrict__ in, float* __restrict__ out) {
    extern __shared__ __align__(16) float s[];   // [SROWS][SCOLS]

    const int tid = threadIdx.x;
    const int x0 = blockIdx.x * TW;
    const int y0 = blockIdx.y * TH;
    const float* __restrict__ base = in + (size_t)blockIdx.z * (IMG_W * IMG_H);

    const bool x_int = (x0 >= PAD) && (x0 + TW + PAD <= IMG_W);
    const bool y_int = (y0 >= PAD) && (y0 + TH + PAD <= IMG_H);

    // ---- Load 148x84 tile ----
    if (x_int) {
        // mapping: rbase = tid/42 (0..11), c2 = tid%42; rows rbase + 12k
        if (tid < 504) {
            const int rbase = tid / 42;
            const int c2 = tid - rbase * 42;
            uint64_t* sp = reinterpret_cast<uint64_t*>(s) + rbase * 42 + c2;
            if (y_int) {
                const uint64_t* g = reinterpret_cast<const uint64_t*>(
                    base + (size_t)(y0 - PAD + rbase) * IMG_W + (x0 - PAD)) + c2;
                #pragma unroll
                for (int k = 0; k < 13; ++k) {
                    if (rbase + 12 * k < SROWS) *sp = __ldg(g);
                    g += 12 * IMG_W / 2;
                    sp += 12 * 42;
                }
            } else {
                #pragma unroll
                for (int k = 0; k < 13; ++k) {
                    int r = rbase + 12 * k;
                    if (r < SROWS) {
                        int gy = reflect_idx(y0 - PAD + r, IMG_H);
                        *sp = __ldg(reinterpret_cast<const uint64_t*>(
                                  base + (size_t)gy * IMG_W + (x0 - PAD)) + c2);
                    }
                    sp += 12 * 42;
                }
            }
        }
    } else {
        int idx = tid;
        #pragma unroll
        for (int it = 0; it < (SROWS * SCOLS + NTHREADS - 1) / NTHREADS; ++it) {
            if (idx < SROWS * SCOLS) {
                int r = idx / SCOLS;
                int c = idx - r * SCOLS;
                int gy = reflect_idx(y0 - PAD + r, IMG_H);
                int gx = reflect_idx(x0 - PAD + c, IMG_W);
                s[r * SCOLS + c] = __ldg(base + (size_t)gy * IMG_W + gx);
            }
            idx += NTHREADS;
        }
    }
    __syncthreads();   // sync 1: tile loaded

    // ---- Horizontal pass, in place, P2 hoisted (3 syncs total) ----
    // P1 units: rows 0..127 (row=tid&127, seg=(tid>>7)*16) - conflict-free octets.
    // P2 units: rows 128..147 (80 units on threads 0..79), computed BEFORE the
    // barrier: P2 reads rows 128..147 which no store touches until after sync 2.
    {
        const int row1 = tid & 127;
        const int seg1 = (tid >> 7) << 4;
        const bool p2 = (tid < 80);
        const int row2 = 128 + (tid % 20);
        const int seg2 = (tid / 20) << 4;

        float o2[16];
        if (p2) hfilter16(&s[row2 * SCOLS + seg2], o2);
        float o1[16];
        hfilter16(&s[row1 * SCOLS + seg1], o1);

        __syncthreads();   // sync 2: ALL raw-tile reads complete

        {
            float4* q = reinterpret_cast<float4*>(&s[row1 * SCOLS + seg1]);
            q[0] = make_float4(o1[0],  o1[1],  o1[2],  o1[3]);
            q[1] = make_float4(o1[4],  o1[5],  o1[6],  o1[7]);
            q[2] = make_float4(o1[8],  o1[9],  o1[10], o1[11]);
            q[3] = make_float4(o1[12], o1[13], o1[14], o1[15]);
        }
        if (p2) {
            float4* q = reinterpret_cast<float4*>(&s[row2 * SCOLS + seg2]);
            q[0] = make_float4(o2[0],  o2[1],  o2[2],  o2[3]);
            q[1] = make_float4(o2[4],  o2[5],  o2[6],  o2[7]);
            q[2] = make_float4(o2[8],  o2[9],  o2[10], o2[11]);
            q[3] = make_float4(o2[12], o2[13], o2[14], o2[15]);
        }
    }
    __syncthreads();   // sync 3: h-tile complete

    // ---- Vertical pass: 32 col-pairs x 16 groups of 8 rows ----
    {
        const int cp = tid & 31;
        const int g = (tid >> 5) << 3;

        uint64_t acc[8];
        #pragma unroll
        for (int o = 0; o < 8; ++o) acc[o] = 0;

        const char* p = reinterpret_cast<const char*>(s + 2 * cp)
                      + (size_t)g * (SCOLS * 4);
        #pragma unroll
        for (int t = 0; t < 28; ++t) {
            uint64_t v2 = *reinterpret_cast<const uint64_t*>(p);
            p += SCOLS * 4;
            #pragma unroll
            for (int o = 0; o < 8; ++o) {
                int j = t - o;
                if (j >= 0 && j < KS) {
                    int wi = (j <= 10) ? j : (20 - j);
                    ffma2(acc[o], v2, bcast2(tap(wi)), acc[o]);
                }
            }
        }

        char* dst = (char*)(out + (size_t)blockIdx.z * (IMG_W * IMG_H)
                                + (size_t)(y0 + g) * IMG_W + (x0 + 2 * cp));
        #pragma unroll
        for (int o = 0; o < 8; ++o) {
            *reinterpret_cast<uint64_t*>(dst) = acc[o];
            dst += IMG_W * 4;
        }
    }
}

extern "C" void kernel_launch(void* const* d_in, const int* in_sizes, int n_in,
                              void* d_out, int out_size) {
    (void)in_sizes; (void)n_in; (void)out_size;
    const float* x = (const float*)d_in[0];
    float* y = (float*)d_out;
    cudaFuncSetAttribute(gauss_blur_fused,
                         cudaFuncAttributeMaxDynamicSharedMemorySize, SMEM_BYTES);
    dim3 grid(IMG_W / TW, IMG_H / TH, NIMG);  // 8 x 4 x 96
    gauss_blur_fused<<<grid, NTHREADS, SMEM_BYTES>>>(x, y);
}

// round 12
// speedup vs baseline: 1.1446x; 1.1446x over previous
#include <cuda_runtime.h>
#include <cstdint>

// FixedGaussianBlur: depthwise 21x21 Gaussian (sigma=3), reflect padding,
// x[32,3,512,512] f32 -> y[32,3,512,512] f32.
// R8 structure (64.2us best) with WARP-OWNED ROWS: each warp loads, filters
// and stores its own 8 rows (warps 0-2 also own the 20 tail rows), so the
// horizontal pass needs only __syncwarp. ONE block barrier total.
// Vertical: packed fma.rn.f32x2 over col pairs (R8 exact).

#define IMG_W 512
#define IMG_H 512
#define PAD 10
#define KS 21
#define TW 64
#define TH 128
#define SROWS 148
#define SCOLS 84
#define NTHREADS 512
#define NIMG 96
#define SMEM_BYTES (SROWS * SCOLS * 4)  // 49728

#define W0  0.13303900f
#define W1  0.12584950f
#define W2  0.10652928f
#define W3  0.08069223f
#define W4  0.05469397f
#define W5  0.03317359f
#define W6  0.01800488f
#define W7  0.00874446f
#define W8  0.00380033f
#define W9  0.00147793f
#define W10 0.00051432f

__device__ __forceinline__ float tap(int j) {
    constexpr float w[KS] = {W10, W9, W8, W7, W6, W5, W4, W3, W2, W1, W0,
                             W1, W2, W3, W4, W5, W6, W7, W8, W9, W10};
    return w[j];
}

__device__ __forceinline__ int reflect_idx(int i, int n) {
    i = (i < 0) ? -i : i;
    i = (i >= n) ? (2 * n - 2 - i) : i;
    return i;
}

__device__ __forceinline__ uint64_t bcast2(float f) {
    uint32_t b = __float_as_uint(f);
    return ((uint64_t)b << 32) | (uint64_t)b;
}

__device__ __forceinline__ void ffma2(uint64_t& d, uint64_t a, uint64_t b, uint64_t c) {
    asm("fma.rn.f32x2 %0, %1, %2, %3;" : "=l"(d) : "l"(a), "l"(b), "l"(c));
}

// 16-output horizontal filter: reads srow[0..35] via 9 LDS.128, scalar FFMA-imm.
__device__ __forceinline__ void hfilter16(const float* srow, float o[16]) {
    float v[36];
    const float4* p = reinterpret_cast<const float4*>(srow);
    #pragma unroll
    for (int q = 0; q < 9; ++q) {
        float4 t = p[q];
        v[4 * q + 0] = t.x; v[4 * q + 1] = t.y;
        v[4 * q + 2] = t.z; v[4 * q + 3] = t.w;
    }
    #pragma unroll
    for (int c = 0; c < 16; ++c) {
        float acc = v[c] * tap(0);
        #pragma unroll
        for (int j = 1; j < KS; ++j) acc = fmaf(v[c + j], tap(j), acc);
        o[c] = acc;
    }
}

// Load one tile row r (smem) from gmem row reflect(y0-PAD+r), warp-cooperative.
__device__ __forceinline__ void load_row_int(float* s, const float* base,
                                             int y0, int x0, int r, int l) {
    int gy = reflect_idx(y0 - PAD + r, IMG_H);
    const uint64_t* g = reinterpret_cast<const uint64_t*>(
        base + (size_t)gy * IMG_W + (x0 - PAD));
    uint64_t* sp = reinterpret_cast<uint64_t*>(s) + r * (SCOLS / 2);
    sp[l] = __ldg(g + l);                       // u64 0..31
    if (l < 10) sp[32 + l] = __ldg(g + 32 + l); // u64 32..41
}

__device__ __forceinline__ void load_row_edge(float* s, const float* base,
                                              int y0, int x0, int r, int l) {
    int gy = reflect_idx(y0 - PAD + r, IMG_H);
    const float* g = base + (size_t)gy * IMG_W;
    #pragma unroll
    for (int c = l; c < SCOLS; c += 32) {
        int gx = reflect_idx(x0 - PAD + c, IMG_W);
        s[r * SCOLS + c] = __ldg(g + gx);
    }
}

__global__ __launch_bounds__(NTHREADS, 3)
void gauss_blur_fused(const float* __restrict__ in, float* __restrict__ out) {
    extern __shared__ __align__(16) float s[];   // [SROWS][SCOLS]

    const int tid = threadIdx.x;
    const int w = tid >> 5;
    const int l = tid & 31;
    const int x0 = blockIdx.x * TW;
    const int y0 = blockIdx.y * TH;
    const float* __restrict__ base = in + (size_t)blockIdx.z * (IMG_W * IMG_H);

    const bool x_int = (x0 >= PAD) && (x0 + TW + PAD <= IMG_W);

    // ---- Warp-owned row loading: warp w owns rows 8w..8w+7; warps 0-2 also
    // own tail rows 128+7w .. (7/7/6 rows). No block barrier needed. ----
    const int r0 = w << 3;
    const int cnt2 = (w == 2) ? 6 : 7;          // tail rows for warps 0..2
    const int rb2 = 128 + w * 7;
    if (x_int) {
        #pragma unroll
        for (int rr = 0; rr < 8; ++rr) load_row_int(s, base, y0, x0, r0 + rr, l);
        if (w < 3) {
            #pragma unroll
            for (int rr = 0; rr < 7; ++rr)
                if (rr < cnt2) load_row_int(s, base, y0, x0, rb2 + rr, l);
        }
    } else {
        #pragma unroll
        for (int rr = 0; rr < 8; ++rr) load_row_edge(s, base, y0, x0, r0 + rr, l);
        if (w < 3) {
            #pragma unroll
            for (int rr = 0; rr < 7; ++rr)
                if (rr < cnt2) load_row_edge(s, base, y0, x0, rb2 + rr, l);
        }
    }
    __syncwarp();   // warp's rows visible to this warp

    // ---- Horizontal pass, in place, warp-local sync only ----
    // lane = seg*8 + dr: octet = 8 consecutive rows, one seg -> conflict-free.
    const int seg = (l >> 3) << 4;              // 0,16,32,48
    const int dr = l & 7;
    {
        const int row = r0 + dr;
        float o[16];
        hfilter16(&s[row * SCOLS + seg], o);
        __syncwarp();   // all reads of this warp's rows complete
        float4* q = reinterpret_cast<float4*>(&s[row * SCOLS + seg]);
        q[0] = make_float4(o[0],  o[1],  o[2],  o[3]);
        q[1] = make_float4(o[4],  o[5],  o[6],  o[7]);
        q[2] = make_float4(o[8],  o[9],  o[10], o[11]);
        q[3] = make_float4(o[12], o[13], o[14], o[15]);
    }
    if (w < 3) {   // tail rows, warp-local second round
        const bool act = (dr < cnt2);
        const int row = rb2 + dr;
        float o[16];
        if (act) hfilter16(&s[row * SCOLS + seg], o);
        __syncwarp();
        if (act) {
            float4* q = reinterpret_cast<float4*>(&s[row * SCOLS + seg]);
            q[0] = make_float4(o[0],  o[1],  o[2],  o[3]);
            q[1] = make_float4(o[4],  o[5],  o[6],  o[7]);
            q[2] = make_float4(o[8],  o[9],  o[10], o[11]);
            q[3] = make_float4(o[12], o[13], o[14], o[15]);
        }
    }

    __syncthreads();   // the ONLY block barrier: h-tile complete

    // ---- Vertical pass: 32 col-pairs x 16 groups of 8 rows (R8 exact) ----
    {
        const int cp = tid & 31;
        const int g = (tid >> 5) << 3;

        uint64_t acc[8];
        #pragma unroll
        for (int o = 0; o < 8; ++o) acc[o] = 0;

        const float* col = s + 2 * cp;
        #pragma unroll
        for (int t = 0; t < 28; ++t) {
            uint64_t v2 = *reinterpret_cast<const uint64_t*>(col + (g + t) * SCOLS);
            #pragma unroll
            for (int o = 0; o < 8; ++o) {
                int j = t - o;
                if (j >= 0 && j < KS) {
                    int wi = (j <= 10) ? j : (20 - j);
                    ffma2(acc[o], v2, bcast2(tap(wi)), acc[o]);
                }
            }
        }

        char* dst = (char*)(out + (size_t)blockIdx.z * (IMG_W * IMG_H)
                                + (size_t)(y0 + g) * IMG_W + (x0 + 2 * cp));
        #pragma unroll
        for (int o = 0; o < 8; ++o) {
            *reinterpret_cast<uint64_t*>(dst) = acc[o];
            dst += IMG_W * 4;
        }
    }
}

extern "C" void kernel_launch(void* const* d_in, const int* in_sizes, int n_in,
                              void* d_out, int out_size) {
    (void)in_sizes; (void)n_in; (void)out_size;
    const float* x = (const float*)d_in[0];
    float* y = (float*)d_out;
    cudaFuncSetAttribute(gauss_blur_fused,
                         cudaFuncAttributeMaxDynamicSharedMemorySize, SMEM_BYTES);
    dim3 grid(IMG_W / TW, IMG_H / TH, NIMG);  // 8 x 4 x 96
    gauss_blur_fused<<<grid, NTHREADS, SMEM_BYTES>>>(x, y);
}